// round 4
// baseline (speedup 1.0000x reference)
#include <cuda_runtime.h>

#define TB 4096
#define CB 1024
#define HB 64

// scratch for projected K/Q/V: [B*T, H] each = 4 MiB each
__device__ float g_q[4 * TB * HB];
__device__ float g_k[4 * TB * HB];
__device__ float g_v[4 * TB * HB];

// ---------------------------------------------------------------------------
// Kernel 1: fused QKV projection.  out = x @ W + b for W in {Wk, Wq, Wv}.
// Grid: 256 blocks (16384 rows / 64), 256 threads.
// Each block: 64 rows x 64 cols for all three matrices.
// Thread (tx,ty) in 16x16: rows 4*ty..+3, cols 4*tx..+3, acc[3][4][4].
// ---------------------------------------------------------------------------
__global__ __launch_bounds__(256) void qkv_kernel(
    const float* __restrict__ x,
    const float* __restrict__ Wk, const float* __restrict__ bk,
    const float* __restrict__ Wq, const float* __restrict__ bq,
    const float* __restrict__ Wv, const float* __restrict__ bv)
{
    __shared__ float xs[64][33];        // x tile [row][k], padded
    __shared__ float ws[3][32][68];     // W tiles [mat][k][col], 16B-aligned rows

    const int tid = threadIdx.x;
    const int tx = tid & 15;
    const int ty = tid >> 4;
    const long row0 = (long)blockIdx.x * 64;

    const float* W[3] = {Wk, Wq, Wv};

    float acc[3][4][4];
#pragma unroll
    for (int m = 0; m < 3; m++)
#pragma unroll
        for (int i = 0; i < 4; i++)
#pragma unroll
            for (int j = 0; j < 4; j++) acc[m][i][j] = 0.f;

    for (int k0 = 0; k0 < CB; k0 += 32) {
        __syncthreads();
        // load x tile: 64 rows x 32 k = 512 float4
#pragma unroll
        for (int f = tid; f < 512; f += 256) {
            int r = f >> 3, c4 = f & 7;
            float4 v = *(const float4*)&x[(row0 + r) * CB + k0 + c4 * 4];
            xs[r][c4 * 4 + 0] = v.x;
            xs[r][c4 * 4 + 1] = v.y;
            xs[r][c4 * 4 + 2] = v.z;
            xs[r][c4 * 4 + 3] = v.w;
        }
        // load W tiles: 3 x (32 k x 64 col) = 3 x 512 float4
#pragma unroll
        for (int m = 0; m < 3; m++) {
#pragma unroll
            for (int f = tid; f < 512; f += 256) {
                int kk = f >> 4, c4 = f & 15;
                *(float4*)&ws[m][kk][c4 * 4] =
                    *(const float4*)&W[m][(long)(k0 + kk) * HB + c4 * 4];
            }
        }
        __syncthreads();

#pragma unroll
        for (int kk = 0; kk < 32; kk++) {
            float xv[4];
#pragma unroll
            for (int i = 0; i < 4; i++) xv[i] = xs[ty * 4 + i][kk];
#pragma unroll
            for (int m = 0; m < 3; m++) {
                float4 wv = *(const float4*)&ws[m][kk][tx * 4];
#pragma unroll
                for (int i = 0; i < 4; i++) {
                    acc[m][i][0] += xv[i] * wv.x;
                    acc[m][i][1] += xv[i] * wv.y;
                    acc[m][i][2] += xv[i] * wv.z;
                    acc[m][i][3] += xv[i] * wv.w;
                }
            }
        }
    }

    float4 bkv = *(const float4*)&bk[tx * 4];
    float4 bqv = *(const float4*)&bq[tx * 4];
    float4 bvv = *(const float4*)&bv[tx * 4];

#pragma unroll
    for (int i = 0; i < 4; i++) {
        long r = row0 + ty * 4 + i;
        float4 o;
        o.x = acc[0][i][0] + bkv.x; o.y = acc[0][i][1] + bkv.y;
        o.z = acc[0][i][2] + bkv.z; o.w = acc[0][i][3] + bkv.w;
        *(float4*)&g_k[r * HB + tx * 4] = o;
        o.x = acc[1][i][0] + bqv.x; o.y = acc[1][i][1] + bqv.y;
        o.z = acc[1][i][2] + bqv.z; o.w = acc[1][i][3] + bqv.w;
        *(float4*)&g_q[r * HB + tx * 4] = o;
        o.x = acc[2][i][0] + bvv.x; o.y = acc[2][i][1] + bvv.y;
        o.z = acc[2][i][2] + bvv.z; o.w = acc[2][i][3] + bvv.w;
        *(float4*)&g_v[r * HB + tx * 4] = o;
    }
}

// ---------------------------------------------------------------------------
// Kernel 2: causal flash attention.
// Grid: (32, 4) = (tile-pair p, batch b), 256 threads.
// Block p handles row tiles {p, 63-p}: (p+1) + (64-p) = 65 inner tiles each
// -> perfect load balance across the causal triangle.
// Thread (tx,ty): rows 4*ty..+3, cols/dims 4*tx..+3.
// ---------------------------------------------------------------------------
#define ATTN_SMEM (4 * 64 * 68 * 4)

__global__ __launch_bounds__(256) void attn_kernel(float* __restrict__ out)
{
    extern __shared__ float smem[];
    float (*qs)[68]  = (float (*)[68])(smem + 0 * 64 * 68); // [row][h]
    float (*kst)[68] = (float (*)[68])(smem + 1 * 64 * 68); // [h][key]  (transposed)
    float (*vs)[68]  = (float (*)[68])(smem + 2 * 64 * 68); // [key][h]
    float (*ps)[68]  = (float (*)[68])(smem + 3 * 64 * 68); // [row][key]

    const int tid = threadIdx.x;
    const int tx = tid & 15;
    const int ty = tid >> 4;
    const int b = blockIdx.y;
    const int p = blockIdx.x;
    const long base = (long)b * TB * HB;
    const float scale = 0.125f;   // 64^-0.5

#pragma unroll 1
    for (int half = 0; half < 2; half++) {
        const int it = half ? (63 - p) : p;

        __syncthreads();
        // load Q tile [64][64]
#pragma unroll
        for (int f = tid; f < 1024; f += 256) {
            int r = f >> 4, c4 = f & 15;
            *(float4*)&qs[r][c4 * 4] =
                *(const float4*)&g_q[base + (long)(it * 64 + r) * HB + c4 * 4];
        }

        float m[4], l[4], acc[4][4];
#pragma unroll
        for (int i = 0; i < 4; i++) {
            m[i] = -1e30f;
            l[i] = 0.f;
#pragma unroll
            for (int j = 0; j < 4; j++) acc[i][j] = 0.f;
        }

        for (int jt = 0; jt <= it; jt++) {
            __syncthreads();
            // load K (transposed -> kst[h][key]) and V tiles
#pragma unroll
            for (int f = tid; f < 1024; f += 256) {
                int s = f >> 4, c4 = f & 15;
                float4 kv = *(const float4*)&g_k[base + (long)(jt * 64 + s) * HB + c4 * 4];
                kst[c4 * 4 + 0][s] = kv.x;
                kst[c4 * 4 + 1][s] = kv.y;
                kst[c4 * 4 + 2][s] = kv.z;
                kst[c4 * 4 + 3][s] = kv.w;
                *(float4*)&vs[s][c4 * 4] =
                    *(const float4*)&g_v[base + (long)(jt * 64 + s) * HB + c4 * 4];
            }
            __syncthreads();

            // S = Q K^T  (64x64x64)
            float s4[4][4];
#pragma unroll
            for (int i = 0; i < 4; i++)
#pragma unroll
                for (int j = 0; j < 4; j++) s4[i][j] = 0.f;

#pragma unroll
            for (int k = 0; k < 64; k++) {
                float qv[4];
#pragma unroll
                for (int i = 0; i < 4; i++) qv[i] = qs[ty * 4 + i][k];
                float4 kv = *(const float4*)&kst[k][tx * 4];
#pragma unroll
                for (int i = 0; i < 4; i++) {
                    s4[i][0] += qv[i] * kv.x;
                    s4[i][1] += qv[i] * kv.y;
                    s4[i][2] += qv[i] * kv.z;
                    s4[i][3] += qv[i] * kv.w;
                }
            }

            // scale + causal mask (only the diagonal tile needs masking)
            if (jt == it) {
#pragma unroll
                for (int i = 0; i < 4; i++)
#pragma unroll
                    for (int j = 0; j < 4; j++)
                        s4[i][j] = (tx * 4 + j > ty * 4 + i) ? -1e30f
                                                             : s4[i][j] * scale;
            } else {
#pragma unroll
                for (int i = 0; i < 4; i++)
#pragma unroll
                    for (int j = 0; j < 4; j++) s4[i][j] *= scale;
            }

            // online softmax update (row groups = 16 lanes sharing ty)
#pragma unroll
            for (int i = 0; i < 4; i++) {
                float mloc = fmaxf(fmaxf(s4[i][0], s4[i][1]),
                                   fmaxf(s4[i][2], s4[i][3]));
#pragma unroll
                for (int o = 8; o >= 1; o >>= 1)
                    mloc = fmaxf(mloc, __shfl_xor_sync(0xffffffffu, mloc, o));
                float mn = fmaxf(m[i], mloc);
                float alpha = __expf(m[i] - mn);
                float lsum = 0.f;
#pragma unroll
                for (int j = 0; j < 4; j++) {
                    s4[i][j] = __expf(s4[i][j] - mn);
                    lsum += s4[i][j];
                }
#pragma unroll
                for (int o = 8; o >= 1; o >>= 1)
                    lsum += __shfl_xor_sync(0xffffffffu, lsum, o);
                l[i] = l[i] * alpha + lsum;
                m[i] = mn;
#pragma unroll
                for (int j = 0; j < 4; j++) acc[i][j] *= alpha;
                *(float4*)&ps[ty * 4 + i][tx * 4] =
                    make_float4(s4[i][0], s4[i][1], s4[i][2], s4[i][3]);
            }
            __syncthreads();

            // O += P V  (64x64x64)
#pragma unroll
            for (int c = 0; c < 64; c++) {
                float pv[4];
#pragma unroll
                for (int i = 0; i < 4; i++) pv[i] = ps[ty * 4 + i][c];
                float4 vv = *(const float4*)&vs[c][tx * 4];
#pragma unroll
                for (int i = 0; i < 4; i++) {
                    acc[i][0] += pv[i] * vv.x;
                    acc[i][1] += pv[i] * vv.y;
                    acc[i][2] += pv[i] * vv.z;
                    acc[i][3] += pv[i] * vv.w;
                }
            }
        }

        // normalize + write
#pragma unroll
        for (int i = 0; i < 4; i++) {
            float inv = 1.f / l[i];
            float4 o = make_float4(acc[i][0] * inv, acc[i][1] * inv,
                                   acc[i][2] * inv, acc[i][3] * inv);
            *(float4*)&out[base + (long)(it * 64 + ty * 4 + i) * HB + tx * 4] = o;
        }
    }
}

extern "C" void kernel_launch(void* const* d_in, const int* in_sizes, int n_in,
                              void* d_out, int out_size)
{
    const float* x  = (const float*)d_in[0];
    const float* Wk = (const float*)d_in[1];
    const float* bk = (const float*)d_in[2];
    const float* Wq = (const float*)d_in[3];
    const float* bq = (const float*)d_in[4];
    const float* Wv = (const float*)d_in[5];
    const float* bv = (const float*)d_in[6];
    float* out = (float*)d_out;

    (void)in_sizes; (void)n_in; (void)out_size;

    static bool attr_done = false;
    if (!attr_done) {
        cudaFuncSetAttribute(attn_kernel,
                             cudaFuncAttributeMaxDynamicSharedMemorySize,
                             ATTN_SMEM);
        attr_done = true;
    }

    qkv_kernel<<<256, 256>>>(x, Wk, bk, Wq, bq, Wv, bv);
    attn_kernel<<<dim3(32, 4), 256, ATTN_SMEM>>>(out);
}

// round 5
// speedup vs baseline: 1.6391x; 1.6391x over previous
#include <cuda_runtime.h>
#include <cstdint>

#define TB 4096
#define CB 1024
#define HB 64

// scratch for projected K/Q/V: [B*T, H] each = 4 MiB each
__device__ float g_q[4 * TB * HB];
__device__ float g_k[4 * TB * HB];
__device__ float g_v[4 * TB * HB];

// ---------------------------------------------------------------------------
// helpers: tf32 convert + m16n8k8 tf32 mma
// ---------------------------------------------------------------------------
__device__ __forceinline__ uint32_t f2tf(float f) {
    uint32_t u;
    asm("cvt.rna.tf32.f32 %0, %1;" : "=r"(u) : "f"(f));
    return u;
}

__device__ __forceinline__ void mma8(float* c, const uint32_t* a,
                                     uint32_t b0, uint32_t b1) {
    asm volatile(
        "mma.sync.aligned.m16n8k8.row.col.f32.tf32.tf32.f32 "
        "{%0,%1,%2,%3}, {%4,%5,%6,%7}, {%8,%9}, {%0,%1,%2,%3};"
        : "+f"(c[0]), "+f"(c[1]), "+f"(c[2]), "+f"(c[3])
        : "r"(a[0]), "r"(a[1]), "r"(a[2]), "r"(a[3]), "r"(b0), "r"(b1));
}

// ---------------------------------------------------------------------------
// Kernel 1: fused QKV projection (unchanged this round).
// ---------------------------------------------------------------------------
__global__ __launch_bounds__(256) void qkv_kernel(
    const float* __restrict__ x,
    const float* __restrict__ Wk, const float* __restrict__ bk,
    const float* __restrict__ Wq, const float* __restrict__ bq,
    const float* __restrict__ Wv, const float* __restrict__ bv)
{
    __shared__ float xs[64][33];
    __shared__ float ws[3][32][68];

    const int tid = threadIdx.x;
    const int tx = tid & 15;
    const int ty = tid >> 4;
    const long row0 = (long)blockIdx.x * 64;

    const float* W[3] = {Wk, Wq, Wv};

    float acc[3][4][4];
#pragma unroll
    for (int m = 0; m < 3; m++)
#pragma unroll
        for (int i = 0; i < 4; i++)
#pragma unroll
            for (int j = 0; j < 4; j++) acc[m][i][j] = 0.f;

    for (int k0 = 0; k0 < CB; k0 += 32) {
        __syncthreads();
#pragma unroll
        for (int f = tid; f < 512; f += 256) {
            int r = f >> 3, c4 = f & 7;
            float4 v = *(const float4*)&x[(row0 + r) * CB + k0 + c4 * 4];
            xs[r][c4 * 4 + 0] = v.x;
            xs[r][c4 * 4 + 1] = v.y;
            xs[r][c4 * 4 + 2] = v.z;
            xs[r][c4 * 4 + 3] = v.w;
        }
#pragma unroll
        for (int m = 0; m < 3; m++) {
#pragma unroll
            for (int f = tid; f < 512; f += 256) {
                int kk = f >> 4, c4 = f & 15;
                *(float4*)&ws[m][kk][c4 * 4] =
                    *(const float4*)&W[m][(long)(k0 + kk) * HB + c4 * 4];
            }
        }
        __syncthreads();

#pragma unroll
        for (int kk = 0; kk < 32; kk++) {
            float xv[4];
#pragma unroll
            for (int i = 0; i < 4; i++) xv[i] = xs[ty * 4 + i][kk];
#pragma unroll
            for (int m = 0; m < 3; m++) {
                float4 wv = *(const float4*)&ws[m][kk][tx * 4];
#pragma unroll
                for (int i = 0; i < 4; i++) {
                    acc[m][i][0] += xv[i] * wv.x;
                    acc[m][i][1] += xv[i] * wv.y;
                    acc[m][i][2] += xv[i] * wv.z;
                    acc[m][i][3] += xv[i] * wv.w;
                }
            }
        }
    }

    float4 bkv = *(const float4*)&bk[tx * 4];
    float4 bqv = *(const float4*)&bq[tx * 4];
    float4 bvv = *(const float4*)&bv[tx * 4];

#pragma unroll
    for (int i = 0; i < 4; i++) {
        long r = row0 + ty * 4 + i;
        float4 o;
        o.x = acc[0][i][0] + bkv.x; o.y = acc[0][i][1] + bkv.y;
        o.z = acc[0][i][2] + bkv.z; o.w = acc[0][i][3] + bkv.w;
        *(float4*)&g_k[r * HB + tx * 4] = o;
        o.x = acc[1][i][0] + bqv.x; o.y = acc[1][i][1] + bqv.y;
        o.z = acc[1][i][2] + bqv.z; o.w = acc[1][i][3] + bqv.w;
        *(float4*)&g_q[r * HB + tx * 4] = o;
        o.x = acc[2][i][0] + bvv.x; o.y = acc[2][i][1] + bvv.y;
        o.z = acc[2][i][2] + bvv.z; o.w = acc[2][i][3] + bvv.w;
        *(float4*)&g_v[r * HB + tx * 4] = o;
    }
}

// ---------------------------------------------------------------------------
// Kernel 2: causal flash attention on tensor cores (tf32 mma.sync).
// Grid (32,4) = (tile pair p, batch). 256 threads = 8 warps in 4x2:
//   warp_r = wid>>1 owns rows 16*warp_r..+15 of the 64x64 tile
//   warp_c = wid&1  owns cols 32*warp_c..+31
// Block p handles row tiles {p, 63-p} -> 65 inner tiles each (balanced).
// ---------------------------------------------------------------------------
#define KS_STR 68
#define VS_STR 72
#define PS_STR 68
// uint32 words: ks 64*68, vs 64*72, ps 64*68, redm 2*64, reds 2*64
#define KS_OFF 0
#define VS_OFF (64 * KS_STR)
#define PS_OFF (VS_OFF + 64 * VS_STR)
#define RM_OFF (PS_OFF + 64 * PS_STR)
#define RS_OFF (RM_OFF + 128)
#define ATTN_SMEM ((RS_OFF + 128) * 4)

__global__ __launch_bounds__(256) void attn_kernel(float* __restrict__ out)
{
    extern __shared__ uint32_t sm[];
    uint32_t* ks = sm + KS_OFF;     // [key][h]   tf32, stride 68
    uint32_t* vs = sm + VS_OFF;     // [key][h]   tf32, stride 72
    uint32_t* ps = sm + PS_OFF;     // [row][key] tf32, stride 68
    float* redm = (float*)(sm + RM_OFF);   // [2][64] partial row max
    float* reds = (float*)(sm + RS_OFF);   // [2][64] partial row sum

    const int tid  = threadIdx.x;
    const int lane = tid & 31;
    const int wid  = tid >> 5;
    const int wr   = wid >> 1;         // 0..3
    const int wc   = wid & 1;          // 0..1
    const int g    = lane >> 2;        // groupID 0..7
    const int tig  = lane & 3;         // 0..3

    const int b = blockIdx.y;
    const int p = blockIdx.x;
    const long base = (long)b * TB * HB;
    const float scale = 0.125f;

    const int lr0 = 16 * wr + g;       // local low row
    const int lr1 = lr0 + 8;           // local high row

#pragma unroll 1
    for (int half = 0; half < 2; half++) {
        const int it = half ? (63 - p) : p;

        // ---- Q fragments for this 64-row tile, straight from global ----
        uint32_t aq[8][4];
        {
            const float* qp = g_q + base + (long)(it * 64) * HB;
#pragma unroll
            for (int k = 0; k < 8; k++) {
                int c0 = k * 8 + tig;
                aq[k][0] = f2tf(qp[lr0 * HB + c0]);
                aq[k][1] = f2tf(qp[lr1 * HB + c0]);
                aq[k][2] = f2tf(qp[lr0 * HB + c0 + 4]);
                aq[k][3] = f2tf(qp[lr1 * HB + c0 + 4]);
            }
        }

        float m0 = -1e30f, m1 = -1e30f, l0 = 0.f, l1 = 0.f;
        float acc[4][4];
#pragma unroll
        for (int nt = 0; nt < 4; nt++)
#pragma unroll
            for (int c = 0; c < 4; c++) acc[nt][c] = 0.f;

        for (int jt = 0; jt <= it; jt++) {
            __syncthreads();   // prior PV reads of ks/vs/ps complete
            // ---- load K,V tiles, converting fp32 -> tf32 on the fly ----
            {
                const float* kp = g_k + base + (long)(jt * 64) * HB;
                const float* vp = g_v + base + (long)(jt * 64) * HB;
#pragma unroll
                for (int f = tid; f < 1024; f += 256) {
                    int r = f >> 4, c4 = (f & 15) * 4;
                    float4 kv = *(const float4*)&kp[r * HB + c4];
                    uint4 ku = make_uint4(f2tf(kv.x), f2tf(kv.y),
                                          f2tf(kv.z), f2tf(kv.w));
                    *(uint4*)&ks[r * KS_STR + c4] = ku;
                    float4 vv = *(const float4*)&vp[r * HB + c4];
                    uint4 vu = make_uint4(f2tf(vv.x), f2tf(vv.y),
                                          f2tf(vv.z), f2tf(vv.w));
                    *(uint4*)&vs[r * VS_STR + c4] = vu;
                }
            }
            __syncthreads();

            // ---- S = Q K^T : warp computes 16x32 via 4 n-tiles x 8 k ----
            float sfr[4][4];
#pragma unroll
            for (int nt = 0; nt < 4; nt++)
#pragma unroll
                for (int c = 0; c < 4; c++) sfr[nt][c] = 0.f;

#pragma unroll
            for (int nt = 0; nt < 4; nt++) {
                const uint32_t* krow = &ks[(32 * wc + 8 * nt + g) * KS_STR];
#pragma unroll
                for (int k = 0; k < 8; k++) {
                    uint32_t b0 = krow[8 * k + tig];
                    uint32_t b1 = krow[8 * k + tig + 4];
                    mma8(sfr[nt], aq[k], b0, b1);
                }
            }

            // ---- scale + causal mask (diagonal tile only) ----
            if (jt == it) {
#pragma unroll
                for (int nt = 0; nt < 4; nt++) {
                    int c0 = 32 * wc + 8 * nt + 2 * tig;
#pragma unroll
                    for (int c = 0; c < 4; c++) {
                        int lc = c0 + (c & 1);
                        int lr = (c < 2) ? lr0 : lr1;
                        sfr[nt][c] = (lc > lr) ? -1e30f : sfr[nt][c] * scale;
                    }
                }
            } else {
#pragma unroll
                for (int nt = 0; nt < 4; nt++)
#pragma unroll
                    for (int c = 0; c < 4; c++) sfr[nt][c] *= scale;
            }

            // ---- partial row max (this warp's 32 cols) ----
            float pm0 = -1e30f, pm1 = -1e30f;
#pragma unroll
            for (int nt = 0; nt < 4; nt++) {
                pm0 = fmaxf(pm0, fmaxf(sfr[nt][0], sfr[nt][1]));
                pm1 = fmaxf(pm1, fmaxf(sfr[nt][2], sfr[nt][3]));
            }
            pm0 = fmaxf(pm0, __shfl_xor_sync(0xffffffffu, pm0, 1));
            pm0 = fmaxf(pm0, __shfl_xor_sync(0xffffffffu, pm0, 2));
            pm1 = fmaxf(pm1, __shfl_xor_sync(0xffffffffu, pm1, 1));
            pm1 = fmaxf(pm1, __shfl_xor_sync(0xffffffffu, pm1, 2));
            if (tig == 0) {
                redm[wc * 64 + lr0] = pm0;
                redm[wc * 64 + lr1] = pm1;
            }
            __syncthreads();

            // ---- combine max across warp halves; exp; stage P; rescale O --
            float mn0 = fmaxf(m0, fmaxf(redm[lr0], redm[64 + lr0]));
            float mn1 = fmaxf(m1, fmaxf(redm[lr1], redm[64 + lr1]));
            float al0 = __expf(m0 - mn0);
            float al1 = __expf(m1 - mn1);
            m0 = mn0; m1 = mn1;

            float s0 = 0.f, s1 = 0.f;
#pragma unroll
            for (int nt = 0; nt < 4; nt++) {
                float e0 = __expf(sfr[nt][0] - mn0);
                float e1 = __expf(sfr[nt][1] - mn0);
                float e2 = __expf(sfr[nt][2] - mn1);
                float e3 = __expf(sfr[nt][3] - mn1);
                s0 += e0 + e1;
                s1 += e2 + e3;
                int col = 32 * wc + 8 * nt + 2 * tig;
                *(uint2*)&ps[lr0 * PS_STR + col] = make_uint2(f2tf(e0), f2tf(e1));
                *(uint2*)&ps[lr1 * PS_STR + col] = make_uint2(f2tf(e2), f2tf(e3));
                acc[nt][0] *= al0; acc[nt][1] *= al0;
                acc[nt][2] *= al1; acc[nt][3] *= al1;
            }
            s0 += __shfl_xor_sync(0xffffffffu, s0, 1);
            s0 += __shfl_xor_sync(0xffffffffu, s0, 2);
            s1 += __shfl_xor_sync(0xffffffffu, s1, 1);
            s1 += __shfl_xor_sync(0xffffffffu, s1, 2);
            if (tig == 0) {
                reds[wc * 64 + lr0] = s0;
                reds[wc * 64 + lr1] = s1;
            }
            __syncthreads();

            l0 = l0 * al0 + reds[lr0] + reds[64 + lr0];
            l1 = l1 * al1 + reds[lr1] + reds[64 + lr1];

            // ---- O += P V : 16x32 per warp, 4 n-tiles x 8 k ----
#pragma unroll
            for (int k = 0; k < 8; k++) {
                uint32_t ap[4];
                ap[0] = ps[lr0 * PS_STR + 8 * k + tig];
                ap[1] = ps[lr1 * PS_STR + 8 * k + tig];
                ap[2] = ps[lr0 * PS_STR + 8 * k + tig + 4];
                ap[3] = ps[lr1 * PS_STR + 8 * k + tig + 4];
                const uint32_t* v0 = &vs[(8 * k + tig) * VS_STR + 32 * wc];
                const uint32_t* v1 = &vs[(8 * k + tig + 4) * VS_STR + 32 * wc];
#pragma unroll
                for (int nt = 0; nt < 4; nt++)
                    mma8(acc[nt], ap, v0[8 * nt + g], v1[8 * nt + g]);
            }
        }

        // ---- normalize + write ----
        float inv0 = 1.f / l0;
        float inv1 = 1.f / l1;
        float* op = out + base + (long)(it * 64) * HB;
#pragma unroll
        for (int nt = 0; nt < 4; nt++) {
            int col = 32 * wc + 8 * nt + 2 * tig;
            *(float2*)&op[lr0 * HB + col] =
                make_float2(acc[nt][0] * inv0, acc[nt][1] * inv0);
            *(float2*)&op[lr1 * HB + col] =
                make_float2(acc[nt][2] * inv1, acc[nt][3] * inv1);
        }
    }
}

extern "C" void kernel_launch(void* const* d_in, const int* in_sizes, int n_in,
                              void* d_out, int out_size)
{
    const float* x  = (const float*)d_in[0];
    const float* Wk = (const float*)d_in[1];
    const float* bk = (const float*)d_in[2];
    const float* Wq = (const float*)d_in[3];
    const float* bq = (const float*)d_in[4];
    const float* Wv = (const float*)d_in[5];
    const float* bv = (const float*)d_in[6];
    float* out = (float*)d_out;

    (void)in_sizes; (void)n_in; (void)out_size;

    static bool attr_done = false;
    if (!attr_done) {
        cudaFuncSetAttribute(attn_kernel,
                             cudaFuncAttributeMaxDynamicSharedMemorySize,
                             ATTN_SMEM);
        attr_done = true;
    }

    qkv_kernel<<<256, 256>>>(x, Wk, bk, Wq, bq, Wv, bv);
    attn_kernel<<<dim3(32, 4), 256, ATTN_SMEM>>>(out);
}

// round 6
// speedup vs baseline: 2.7461x; 1.6754x over previous
#include <cuda_runtime.h>
#include <cstdint>

#define TB 4096
#define CB 1024
#define HB 64

// scratch for projected K/Q/V: [B*T, H] each = 4 MiB each
__device__ float g_q[4 * TB * HB];
__device__ float g_k[4 * TB * HB];
__device__ float g_v[4 * TB * HB];

// ---------------------------------------------------------------------------
// helpers: tf32 convert + m16n8k8 tf32 mma
// ---------------------------------------------------------------------------
__device__ __forceinline__ uint32_t f2tf(float f) {
    uint32_t u;
    asm("cvt.rna.tf32.f32 %0, %1;" : "=r"(u) : "f"(f));
    return u;
}

__device__ __forceinline__ void mma8(float* c, const uint32_t* a,
                                     uint32_t b0, uint32_t b1) {
    asm volatile(
        "mma.sync.aligned.m16n8k8.row.col.f32.tf32.tf32.f32 "
        "{%0,%1,%2,%3}, {%4,%5,%6,%7}, {%8,%9}, {%0,%1,%2,%3};"
        : "+f"(c[0]), "+f"(c[1]), "+f"(c[2]), "+f"(c[3])
        : "r"(a[0]), "r"(a[1]), "r"(a[2]), "r"(a[3]), "r"(b0), "r"(b1));
}

// ---------------------------------------------------------------------------
// Kernel 1: fused QKV projection on tensor cores (tf32).
// out = x @ [Wk|Wq|Wv] + bias.  Grid 256 (row tiles of 64), 256 threads.
// 8 warps in 4x2: warp rows 16*wr.., cols 96*wc..  (192 total cols = 3 mats).
// K loop in chunks of 32 with register prefetch double-buffering.
// ---------------------------------------------------------------------------
#define XS_STR 36
#define WS_STR 200

__global__ __launch_bounds__(256) void qkv_kernel(
    const float* __restrict__ x,
    const float* __restrict__ Wk, const float* __restrict__ bk,
    const float* __restrict__ Wq, const float* __restrict__ bq,
    const float* __restrict__ Wv, const float* __restrict__ bv)
{
    __shared__ uint32_t xs[64 * XS_STR];   // x tile [row][k] tf32
    __shared__ uint32_t ws[32 * WS_STR];   // W tile [k][3*64 cols] tf32

    const int tid  = threadIdx.x;
    const int lane = tid & 31;
    const int wid  = tid >> 5;
    const int wr   = wid >> 1;        // 0..3
    const int wc   = wid & 1;         // 0..1
    const int g    = lane >> 2;       // 0..7
    const int tig  = lane & 3;        // 0..3
    const long row0 = (long)blockIdx.x * 64;

    float acc[12][4];
#pragma unroll
    for (int nt = 0; nt < 12; nt++)
#pragma unroll
        for (int c = 0; c < 4; c++) acc[nt][c] = 0.f;

    float4 px[2], pw[6];

    // prefetch helpers (macros so indices stay compile-time where possible)
#define QKV_LOAD(k0_)                                                        \
    {                                                                        \
        _Pragma("unroll")                                                    \
        for (int i = 0; i < 2; i++) {                                        \
            int f = tid + 256 * i;                                           \
            int r = f >> 3, c = (f & 7) * 4;                                 \
            px[i] = *(const float4*)&x[(row0 + r) * CB + (k0_) + c];         \
        }                                                                    \
        _Pragma("unroll")                                                    \
        for (int i = 0; i < 6; i++) {                                        \
            int f = tid + 256 * i;                                           \
            int m = f >> 9, kk = (f >> 4) & 31, c = (f & 15) * 4;            \
            const float* wp = (m == 0) ? Wk : ((m == 1) ? Wq : Wv);          \
            pw[i] = *(const float4*)&wp[(long)((k0_) + kk) * HB + c];        \
        }                                                                    \
    }

    QKV_LOAD(0);

    for (int k0 = 0; k0 < CB; k0 += 32) {
        __syncthreads();
        // commit prefetched chunk to smem (fp32 -> tf32)
#pragma unroll
        for (int i = 0; i < 2; i++) {
            int f = tid + 256 * i;
            int r = f >> 3, c = (f & 7) * 4;
            *(uint4*)&xs[r * XS_STR + c] =
                make_uint4(f2tf(px[i].x), f2tf(px[i].y),
                           f2tf(px[i].z), f2tf(px[i].w));
        }
#pragma unroll
        for (int i = 0; i < 6; i++) {
            int f = tid + 256 * i;
            int m = f >> 9, kk = (f >> 4) & 31, c = (f & 15) * 4;
            *(uint4*)&ws[kk * WS_STR + m * 64 + c] =
                make_uint4(f2tf(pw[i].x), f2tf(pw[i].y),
                           f2tf(pw[i].z), f2tf(pw[i].w));
        }
        __syncthreads();

        if (k0 + 32 < CB) QKV_LOAD(k0 + 32);

        const int r0 = 16 * wr + g;
#pragma unroll
        for (int kk8 = 0; kk8 < 4; kk8++) {
            uint32_t a[4];
            a[0] = xs[r0 * XS_STR + 8 * kk8 + tig];
            a[1] = xs[(r0 + 8) * XS_STR + 8 * kk8 + tig];
            a[2] = xs[r0 * XS_STR + 8 * kk8 + tig + 4];
            a[3] = xs[(r0 + 8) * XS_STR + 8 * kk8 + tig + 4];
            const uint32_t* w0 = &ws[(8 * kk8 + tig) * WS_STR + 96 * wc];
            const uint32_t* w1 = &ws[(8 * kk8 + tig + 4) * WS_STR + 96 * wc];
#pragma unroll
            for (int nt = 0; nt < 12; nt++)
                mma8(acc[nt], a, w0[8 * nt + g], w1[8 * nt + g]);
        }
    }

    // epilogue: add bias, scatter to g_k / g_q / g_v
    const int r0 = 16 * wr + g;
#pragma unroll
    for (int nt = 0; nt < 12; nt++) {
        int gcol = 96 * wc + 8 * nt + 2 * tig;
        int m = gcol >> 6, lc = gcol & 63;
        const float* bp = (m == 0) ? bk : ((m == 1) ? bq : bv);
        float* op = (m == 0) ? g_k : ((m == 1) ? g_q : g_v);
        float b0 = bp[lc], b1 = bp[lc + 1];
        float* o = op + (row0 + r0) * HB + lc;
        *(float2*)o = make_float2(acc[nt][0] + b0, acc[nt][1] + b1);
        *(float2*)(o + 8 * HB) = make_float2(acc[nt][2] + b0, acc[nt][3] + b1);
    }
}

// ---------------------------------------------------------------------------
// Kernel 2: causal flash attention on tensor cores (tf32 mma.sync),
// with register-prefetch double-buffering of K/V staging.
// Grid (32,4) = (tile pair p, batch). 256 threads = 8 warps in 4x2.
// Block p handles row tiles {p, 63-p} -> 65 inner tiles each (balanced).
// ---------------------------------------------------------------------------
#define KS_STR 68
#define VS_STR 72
#define PS_STR 68
#define KS_OFF 0
#define VS_OFF (64 * KS_STR)
#define PS_OFF (VS_OFF + 64 * VS_STR)
#define RM_OFF (PS_OFF + 64 * PS_STR)
#define RS_OFF (RM_OFF + 128)
#define ATTN_SMEM ((RS_OFF + 128) * 4)

__global__ __launch_bounds__(256) void attn_kernel(float* __restrict__ out)
{
    extern __shared__ uint32_t sm[];
    uint32_t* ks = sm + KS_OFF;     // [key][h]   tf32, stride 68
    uint32_t* vs = sm + VS_OFF;     // [key][h]   tf32, stride 72
    uint32_t* ps = sm + PS_OFF;     // [row][key] tf32, stride 68
    float* redm = (float*)(sm + RM_OFF);   // [2][64] partial row max
    float* reds = (float*)(sm + RS_OFF);   // [2][64] partial row sum

    const int tid  = threadIdx.x;
    const int lane = tid & 31;
    const int wid  = tid >> 5;
    const int wr   = wid >> 1;
    const int wc   = wid & 1;
    const int g    = lane >> 2;
    const int tig  = lane & 3;

    const int b = blockIdx.y;
    const int p = blockIdx.x;
    const long base = (long)b * TB * HB;
    const float scale = 0.125f;

    const int lr0 = 16 * wr + g;
    const int lr1 = lr0 + 8;

    float4 pkr[4], pvr[4];   // prefetch registers for next K/V tile

#define ATTN_LOAD(jt_)                                                       \
    {                                                                        \
        const float* kp = g_k + base + (long)((jt_) * 64) * HB;              \
        const float* vp = g_v + base + (long)((jt_) * 64) * HB;              \
        _Pragma("unroll")                                                    \
        for (int i = 0; i < 4; i++) {                                        \
            int f = tid + 256 * i;                                           \
            int r = f >> 4, c = (f & 15) * 4;                                \
            pkr[i] = *(const float4*)&kp[r * HB + c];                        \
            pvr[i] = *(const float4*)&vp[r * HB + c];                        \
        }                                                                    \
    }

#pragma unroll 1
    for (int half = 0; half < 2; half++) {
        const int it = half ? (63 - p) : p;

        // ---- Q fragments for this 64-row tile, straight from global ----
        uint32_t aq[8][4];
        {
            const float* qp = g_q + base + (long)(it * 64) * HB;
#pragma unroll
            for (int k = 0; k < 8; k++) {
                int c0 = k * 8 + tig;
                aq[k][0] = f2tf(qp[lr0 * HB + c0]);
                aq[k][1] = f2tf(qp[lr1 * HB + c0]);
                aq[k][2] = f2tf(qp[lr0 * HB + c0 + 4]);
                aq[k][3] = f2tf(qp[lr1 * HB + c0 + 4]);
            }
        }

        float m0 = -1e30f, m1 = -1e30f, l0 = 0.f, l1 = 0.f;
        float acc[4][4];
#pragma unroll
        for (int nt = 0; nt < 4; nt++)
#pragma unroll
            for (int c = 0; c < 4; c++) acc[nt][c] = 0.f;

        ATTN_LOAD(0);

        for (int jt = 0; jt <= it; jt++) {
            __syncthreads();   // prior PV reads of ks/vs complete
            // ---- commit prefetched K,V tile (fp32 -> tf32) ----
#pragma unroll
            for (int i = 0; i < 4; i++) {
                int f = tid + 256 * i;
                int r = f >> 4, c = (f & 15) * 4;
                *(uint4*)&ks[r * KS_STR + c] =
                    make_uint4(f2tf(pkr[i].x), f2tf(pkr[i].y),
                               f2tf(pkr[i].z), f2tf(pkr[i].w));
                *(uint4*)&vs[r * VS_STR + c] =
                    make_uint4(f2tf(pvr[i].x), f2tf(pvr[i].y),
                               f2tf(pvr[i].z), f2tf(pvr[i].w));
            }
            __syncthreads();

            if (jt < it) ATTN_LOAD(jt + 1);

            // ---- S = Q K^T : warp computes 16x32 via 4 n-tiles x 8 k ----
            float sfr[4][4];
#pragma unroll
            for (int nt = 0; nt < 4; nt++)
#pragma unroll
                for (int c = 0; c < 4; c++) sfr[nt][c] = 0.f;

#pragma unroll
            for (int nt = 0; nt < 4; nt++) {
                const uint32_t* krow = &ks[(32 * wc + 8 * nt + g) * KS_STR];
#pragma unroll
                for (int k = 0; k < 8; k++) {
                    uint32_t b0 = krow[8 * k + tig];
                    uint32_t b1 = krow[8 * k + tig + 4];
                    mma8(sfr[nt], aq[k], b0, b1);
                }
            }

            // ---- scale + causal mask (diagonal tile only) ----
            if (jt == it) {
#pragma unroll
                for (int nt = 0; nt < 4; nt++) {
                    int c0 = 32 * wc + 8 * nt + 2 * tig;
#pragma unroll
                    for (int c = 0; c < 4; c++) {
                        int lc = c0 + (c & 1);
                        int lr = (c < 2) ? lr0 : lr1;
                        sfr[nt][c] = (lc > lr) ? -1e30f : sfr[nt][c] * scale;
                    }
                }
            } else {
#pragma unroll
                for (int nt = 0; nt < 4; nt++)
#pragma unroll
                    for (int c = 0; c < 4; c++) sfr[nt][c] *= scale;
            }

            // ---- partial row max (this warp's 32 cols) ----
            float pm0 = -1e30f, pm1 = -1e30f;
#pragma unroll
            for (int nt = 0; nt < 4; nt++) {
                pm0 = fmaxf(pm0, fmaxf(sfr[nt][0], sfr[nt][1]));
                pm1 = fmaxf(pm1, fmaxf(sfr[nt][2], sfr[nt][3]));
            }
            pm0 = fmaxf(pm0, __shfl_xor_sync(0xffffffffu, pm0, 1));
            pm0 = fmaxf(pm0, __shfl_xor_sync(0xffffffffu, pm0, 2));
            pm1 = fmaxf(pm1, __shfl_xor_sync(0xffffffffu, pm1, 1));
            pm1 = fmaxf(pm1, __shfl_xor_sync(0xffffffffu, pm1, 2));
            if (tig == 0) {
                redm[wc * 64 + lr0] = pm0;
                redm[wc * 64 + lr1] = pm1;
            }
            __syncthreads();

            // ---- combine max across warp halves; exp; stage P; rescale O --
            float mn0 = fmaxf(m0, fmaxf(redm[lr0], redm[64 + lr0]));
            float mn1 = fmaxf(m1, fmaxf(redm[lr1], redm[64 + lr1]));
            float al0 = __expf(m0 - mn0);
            float al1 = __expf(m1 - mn1);
            m0 = mn0; m1 = mn1;

            float s0 = 0.f, s1 = 0.f;
#pragma unroll
            for (int nt = 0; nt < 4; nt++) {
                float e0 = __expf(sfr[nt][0] - mn0);
                float e1 = __expf(sfr[nt][1] - mn0);
                float e2 = __expf(sfr[nt][2] - mn1);
                float e3 = __expf(sfr[nt][3] - mn1);
                s0 += e0 + e1;
                s1 += e2 + e3;
                int col = 32 * wc + 8 * nt + 2 * tig;
                *(uint2*)&ps[lr0 * PS_STR + col] = make_uint2(f2tf(e0), f2tf(e1));
                *(uint2*)&ps[lr1 * PS_STR + col] = make_uint2(f2tf(e2), f2tf(e3));
                acc[nt][0] *= al0; acc[nt][1] *= al0;
                acc[nt][2] *= al1; acc[nt][3] *= al1;
            }
            s0 += __shfl_xor_sync(0xffffffffu, s0, 1);
            s0 += __shfl_xor_sync(0xffffffffu, s0, 2);
            s1 += __shfl_xor_sync(0xffffffffu, s1, 1);
            s1 += __shfl_xor_sync(0xffffffffu, s1, 2);
            if (tig == 0) {
                reds[wc * 64 + lr0] = s0;
                reds[wc * 64 + lr1] = s1;
            }
            __syncthreads();

            l0 = l0 * al0 + reds[lr0] + reds[64 + lr0];
            l1 = l1 * al1 + reds[lr1] + reds[64 + lr1];

            // ---- O += P V : 16x32 per warp, 4 n-tiles x 8 k ----
#pragma unroll
            for (int k = 0; k < 8; k++) {
                uint32_t ap[4];
                ap[0] = ps[lr0 * PS_STR + 8 * k + tig];
                ap[1] = ps[lr1 * PS_STR + 8 * k + tig];
                ap[2] = ps[lr0 * PS_STR + 8 * k + tig + 4];
                ap[3] = ps[lr1 * PS_STR + 8 * k + tig + 4];
                const uint32_t* v0 = &vs[(8 * k + tig) * VS_STR + 32 * wc];
                const uint32_t* v1 = &vs[(8 * k + tig + 4) * VS_STR + 32 * wc];
#pragma unroll
                for (int nt = 0; nt < 4; nt++)
                    mma8(acc[nt], ap, v0[8 * nt + g], v1[8 * nt + g]);
            }
        }

        // ---- normalize + write ----
        float inv0 = 1.f / l0;
        float inv1 = 1.f / l1;
        float* op = out + base + (long)(it * 64) * HB;
#pragma unroll
        for (int nt = 0; nt < 4; nt++) {
            int col = 32 * wc + 8 * nt + 2 * tig;
            *(float2*)&op[lr0 * HB + col] =
                make_float2(acc[nt][0] * inv0, acc[nt][1] * inv0);
            *(float2*)&op[lr1 * HB + col] =
                make_float2(acc[nt][2] * inv1, acc[nt][3] * inv1);
        }
    }
}

extern "C" void kernel_launch(void* const* d_in, const int* in_sizes, int n_in,
                              void* d_out, int out_size)
{
    const float* x  = (const float*)d_in[0];
    const float* Wk = (const float*)d_in[1];
    const float* bk = (const float*)d_in[2];
    const float* Wq = (const float*)d_in[3];
    const float* bq = (const float*)d_in[4];
    const float* Wv = (const float*)d_in[5];
    const float* bv = (const float*)d_in[6];
    float* out = (float*)d_out;

    (void)in_sizes; (void)n_in; (void)out_size;

    static bool attr_done = false;
    if (!attr_done) {
        cudaFuncSetAttribute(attn_kernel,
                             cudaFuncAttributeMaxDynamicSharedMemorySize,
                             ATTN_SMEM);
        attr_done = true;
    }

    qkv_kernel<<<256, 256>>>(x, Wk, bk, Wq, bq, Wv, bv);
    attn_kernel<<<dim3(32, 4), 256, ATTN_SMEM>>>(out);
}